// round 1
// baseline (speedup 1.0000x reference)
#include <cuda_runtime.h>
#include <math_constants.h>

#define BATCH 4
#define SEQ   2048
#define EMB   1024
#define ADIM  1024

// Scratch (allocation-free rule: __device__ globals)
__device__ float g_Q[BATCH * SEQ * ADIM];                 // 32 MB
__device__ float g_K[BATCH * SEQ * ADIM];                 // 32 MB
__device__ float g_V[BATCH * SEQ * ADIM];                 // 32 MB
__device__ float g_P[(size_t)BATCH * SEQ * SEQ];          // 64 MB

// ---------------------------------------------------------------------------
// Kernel 1: fused QKV projection.  C = X @ W^T  (TN GEMM)
// X: [BATCH*SEQ, EMB] row-major.  W: [ADIM, EMB] row-major.
// 128x128 tile, BK=16, 256 threads, 8x8 per thread.
// ---------------------------------------------------------------------------
__global__ __launch_bounds__(256) void gemm_tn_qkv(
    const float* __restrict__ X,
    const float* __restrict__ Wk,
    const float* __restrict__ Wq,
    const float* __restrict__ Wv)
{
    const int bm = blockIdx.y * 128;   // row tile in [0, BATCH*SEQ)
    const int bn = blockIdx.x * 128;   // col tile in [0, ADIM)

    const float* W;
    float* Cg;
    if      (blockIdx.z == 0) { W = Wk; Cg = g_K; }
    else if (blockIdx.z == 1) { W = Wq; Cg = g_Q; }
    else                      { W = Wv; Cg = g_V; }

    __shared__ float As[16][128];
    __shared__ float Bs[16][128];

    const int tid = threadIdx.x;
    const int tx  = tid % 16;
    const int ty  = tid / 16;
    const int lr  = tid / 4;          // 0..63
    const int lc  = (tid % 4) * 4;    // 0,4,8,12

    float acc[8][8] = {};

    for (int kt = 0; kt < EMB; kt += 16) {
        #pragma unroll
        for (int half = 0; half < 2; ++half) {
            const int row = lr + half * 64;
            float4 va = *(const float4*)(X + (size_t)(bm + row) * EMB + kt + lc);
            As[lc + 0][row] = va.x; As[lc + 1][row] = va.y;
            As[lc + 2][row] = va.z; As[lc + 3][row] = va.w;
            float4 vb = *(const float4*)(W + (size_t)(bn + row) * EMB + kt + lc);
            Bs[lc + 0][row] = vb.x; Bs[lc + 1][row] = vb.y;
            Bs[lc + 2][row] = vb.z; Bs[lc + 3][row] = vb.w;
        }
        __syncthreads();

        #pragma unroll
        for (int kk = 0; kk < 16; ++kk) {
            float a[8], b[8];
            *(float4*)&a[0] = *(const float4*)&As[kk][ty * 8];
            *(float4*)&a[4] = *(const float4*)&As[kk][ty * 8 + 4];
            *(float4*)&b[0] = *(const float4*)&Bs[kk][tx * 8];
            *(float4*)&b[4] = *(const float4*)&Bs[kk][tx * 8 + 4];
            #pragma unroll
            for (int i = 0; i < 8; ++i)
                #pragma unroll
                for (int j = 0; j < 8; ++j)
                    acc[i][j] = fmaf(a[i], b[j], acc[i][j]);
        }
        __syncthreads();
    }

    #pragma unroll
    for (int i = 0; i < 8; ++i) {
        float* crow = Cg + (size_t)(bm + ty * 8 + i) * ADIM + bn + tx * 8;
        *(float4*)(crow)     = make_float4(acc[i][0], acc[i][1], acc[i][2], acc[i][3]);
        *(float4*)(crow + 4) = make_float4(acc[i][4], acc[i][5], acc[i][6], acc[i][7]);
    }
}

// ---------------------------------------------------------------------------
// Kernel 2: causal scores.  P[b,q,k] = (Q[b,q,:] . K[b,k,:]) * scale for k<=q
// TN GEMM per batch; whole tiles strictly above the diagonal are skipped.
// ---------------------------------------------------------------------------
__global__ __launch_bounds__(256) void gemm_scores()
{
    const int b  = blockIdx.z;
    const int bq = blockIdx.y * 128;   // q tile
    const int bk = blockIdx.x * 128;   // k tile
    if (bk > bq + 127) return;         // entirely above the diagonal

    const float* Qp = g_Q + (size_t)b * SEQ * ADIM;
    const float* Kp = g_K + (size_t)b * SEQ * ADIM;

    __shared__ float As[16][128];
    __shared__ float Bs[16][128];

    const int tid = threadIdx.x;
    const int tx  = tid % 16;
    const int ty  = tid / 16;
    const int lr  = tid / 4;
    const int lc  = (tid % 4) * 4;

    float acc[8][8] = {};

    for (int kt = 0; kt < ADIM; kt += 16) {
        #pragma unroll
        for (int half = 0; half < 2; ++half) {
            const int row = lr + half * 64;
            float4 va = *(const float4*)(Qp + (size_t)(bq + row) * ADIM + kt + lc);
            As[lc + 0][row] = va.x; As[lc + 1][row] = va.y;
            As[lc + 2][row] = va.z; As[lc + 3][row] = va.w;
            float4 vb = *(const float4*)(Kp + (size_t)(bk + row) * ADIM + kt + lc);
            Bs[lc + 0][row] = vb.x; Bs[lc + 1][row] = vb.y;
            Bs[lc + 2][row] = vb.z; Bs[lc + 3][row] = vb.w;
        }
        __syncthreads();

        #pragma unroll
        for (int kk = 0; kk < 16; ++kk) {
            float a[8], bb[8];
            *(float4*)&a[0]  = *(const float4*)&As[kk][ty * 8];
            *(float4*)&a[4]  = *(const float4*)&As[kk][ty * 8 + 4];
            *(float4*)&bb[0] = *(const float4*)&Bs[kk][tx * 8];
            *(float4*)&bb[4] = *(const float4*)&Bs[kk][tx * 8 + 4];
            #pragma unroll
            for (int i = 0; i < 8; ++i)
                #pragma unroll
                for (int j = 0; j < 8; ++j)
                    acc[i][j] = fmaf(a[i], bb[j], acc[i][j]);
        }
        __syncthreads();
    }

    const float scale = 0.03125f;  // 1/sqrt(1024)
    float* Pb = g_P + (size_t)b * SEQ * SEQ;

    if (bk + 127 <= bq) {
        // strictly lower tile: vectorized store
        #pragma unroll
        for (int i = 0; i < 8; ++i) {
            const int q = bq + ty * 8 + i;
            float* prow = Pb + (size_t)q * SEQ + bk + tx * 8;
            *(float4*)(prow)     = make_float4(acc[i][0] * scale, acc[i][1] * scale,
                                               acc[i][2] * scale, acc[i][3] * scale);
            *(float4*)(prow + 4) = make_float4(acc[i][4] * scale, acc[i][5] * scale,
                                               acc[i][6] * scale, acc[i][7] * scale);
        }
    } else {
        // diagonal tile: masked scalar stores
        const float NEG_INF = -CUDART_INF_F;
        #pragma unroll
        for (int i = 0; i < 8; ++i) {
            const int q = bq + ty * 8 + i;
            float* prow = Pb + (size_t)q * SEQ;
            #pragma unroll
            for (int j = 0; j < 8; ++j) {
                const int k = bk + tx * 8 + j;
                prow[k] = (k <= q) ? acc[i][j] * scale : NEG_INF;
            }
        }
    }
}

// ---------------------------------------------------------------------------
// Kernel 3: row softmax over k in [0, q], zero-fill k in (q, SEQ).
// One block (256 threads) per row.
// ---------------------------------------------------------------------------
__global__ __launch_bounds__(256) void softmax_rows()
{
    const int row = blockIdx.x;           // 0 .. BATCH*SEQ-1
    const int b   = row / SEQ;
    const int q   = row % SEQ;
    float* p = g_P + (size_t)b * SEQ * SEQ + (size_t)q * SEQ;
    const int n  = q + 1;

    const int tid  = threadIdx.x;
    const int lane = tid & 31;
    const int wid  = tid >> 5;
    __shared__ float red[8];

    // pass 1: max
    float m = -CUDART_INF_F;
    for (int k = tid; k < n; k += 256) m = fmaxf(m, p[k]);
    #pragma unroll
    for (int o = 16; o > 0; o >>= 1) m = fmaxf(m, __shfl_xor_sync(0xffffffffu, m, o));
    if (lane == 0) red[wid] = m;
    __syncthreads();
    float rowmax = red[0];
    #pragma unroll
    for (int i = 1; i < 8; ++i) rowmax = fmaxf(rowmax, red[i]);
    __syncthreads();

    // pass 2: exp + sum (store exp in place)
    float s = 0.0f;
    for (int k = tid; k < n; k += 256) {
        float e = expf(p[k] - rowmax);
        p[k] = e;
        s += e;
    }
    #pragma unroll
    for (int o = 16; o > 0; o >>= 1) s += __shfl_xor_sync(0xffffffffu, s, o);
    if (lane == 0) red[wid] = s;
    __syncthreads();
    float rowsum = 0.0f;
    #pragma unroll
    for (int i = 0; i < 8; ++i) rowsum += red[i];
    const float inv = 1.0f / rowsum;

    // pass 3: normalize + zero-fill upper part
    for (int k = tid; k < n; k += 256) p[k] *= inv;
    for (int k = n + tid; k < SEQ; k += 256) p[k] = 0.0f;
}

// ---------------------------------------------------------------------------
// Kernel 4: out = P @ V  (NN GEMM per batch), K-loop clipped at q-tile end.
// Epilogue: round to 4 decimals (half-to-even, matching jnp.round).
// ---------------------------------------------------------------------------
__global__ __launch_bounds__(256) void gemm_av(float* __restrict__ out)
{
    const int b  = blockIdx.z;
    const int bm = blockIdx.y * 128;  // q tile
    const int bn = blockIdx.x * 128;  // attn-dim tile

    const float* Ap = g_P + (size_t)b * SEQ * SEQ;    // [SEQ, SEQ]
    const float* Bp = g_V + (size_t)b * SEQ * ADIM;   // [SEQ, ADIM]
    float* Cp = out + (size_t)b * SEQ * ADIM;

    __shared__ float As[16][128];
    __shared__ float Bs[16][128];

    const int tid = threadIdx.x;
    const int tx  = tid % 16;
    const int ty  = tid / 16;
    const int lr  = tid / 4;          // A-tile loader
    const int lc  = (tid % 4) * 4;
    const int br  = tid / 32;         // B-tile loader: row 0..7 (+8)
    const int bc  = (tid % 32) * 4;   // col 0..124

    float acc[8][8] = {};

    const int kend = bm + 128;        // P[q,k] == 0 for k > q, so clip K loop

    for (int kt = 0; kt < kend; kt += 16) {
        #pragma unroll
        for (int half = 0; half < 2; ++half) {
            const int arow = lr + half * 64;
            float4 va = *(const float4*)(Ap + (size_t)(bm + arow) * SEQ + kt + lc);
            As[lc + 0][arow] = va.x; As[lc + 1][arow] = va.y;
            As[lc + 2][arow] = va.z; As[lc + 3][arow] = va.w;
            const int brow = br + half * 8;
            float4 vb = *(const float4*)(Bp + (size_t)(kt + brow) * ADIM + bn + bc);
            *(float4*)&Bs[brow][bc] = vb;
        }
        __syncthreads();

        #pragma unroll
        for (int kk = 0; kk < 16; ++kk) {
            float a[8], bb[8];
            *(float4*)&a[0]  = *(const float4*)&As[kk][ty * 8];
            *(float4*)&a[4]  = *(const float4*)&As[kk][ty * 8 + 4];
            *(float4*)&bb[0] = *(const float4*)&Bs[kk][tx * 8];
            *(float4*)&bb[4] = *(const float4*)&Bs[kk][tx * 8 + 4];
            #pragma unroll
            for (int i = 0; i < 8; ++i)
                #pragma unroll
                for (int j = 0; j < 8; ++j)
                    acc[i][j] = fmaf(a[i], bb[j], acc[i][j]);
        }
        __syncthreads();
    }

    #pragma unroll
    for (int i = 0; i < 8; ++i) {
        float* crow = Cp + (size_t)(bm + ty * 8 + i) * ADIM + bn + tx * 8;
        float v[8];
        #pragma unroll
        for (int j = 0; j < 8; ++j) v[j] = rintf(acc[i][j] * 1.0e4f) * 1.0e-4f;
        *(float4*)(crow)     = make_float4(v[0], v[1], v[2], v[3]);
        *(float4*)(crow + 4) = make_float4(v[4], v[5], v[6], v[7]);
    }
}

// ---------------------------------------------------------------------------
extern "C" void kernel_launch(void* const* d_in, const int* in_sizes, int n_in,
                              void* d_out, int out_size)
{
    const float* X  = (const float*)d_in[0];  // embedded [4,2048,1024]
    const float* Wk = (const float*)d_in[1];  // W_k [1024,1024]
    const float* Wq = (const float*)d_in[2];  // W_q [1024,1024]
    const float* Wv = (const float*)d_in[3];  // W_v [1024,1024]
    float* out = (float*)d_out;               // [4,2048,1024] fp32

    gemm_tn_qkv<<<dim3(ADIM / 128, (BATCH * SEQ) / 128, 3), 256>>>(X, Wk, Wq, Wv);
    gemm_scores<<<dim3(SEQ / 128, SEQ / 128, BATCH), 256>>>();
    softmax_rows<<<BATCH * SEQ, 256>>>();
    gemm_av<<<dim3(ADIM / 128, SEQ / 128, BATCH), 256>>>(out);
}

// round 3
// speedup vs baseline: 3.2143x; 3.2143x over previous
#include <cuda_runtime.h>
#include <cuda_bf16.h>
#include <math_constants.h>
#include <cstdint>

#define BATCH 4
#define SEQ   2048
#define EMB   1024
#define ADIM  1024
#define BSEQ  (BATCH * SEQ)

// ---------------------------------------------------------------------------
// Scratch (__device__ globals per allocation-free rule)
// ---------------------------------------------------------------------------
__device__ __align__(16) __nv_bfloat16 g_Xhi[BSEQ * EMB];
__device__ __align__(16) __nv_bfloat16 g_Xlo[BSEQ * EMB];
__device__ __align__(16) __nv_bfloat16 g_Whi[3 * ADIM * EMB];
__device__ __align__(16) __nv_bfloat16 g_Wlo[3 * ADIM * EMB];
__device__ __align__(16) __nv_bfloat16 g_Qhi[BSEQ * ADIM];
__device__ __align__(16) __nv_bfloat16 g_Qlo[BSEQ * ADIM];
__device__ __align__(16) __nv_bfloat16 g_Khi[BSEQ * ADIM];
__device__ __align__(16) __nv_bfloat16 g_Klo[BSEQ * ADIM];
__device__ __align__(16) __nv_bfloat16 g_Vthi[BATCH * ADIM * SEQ];  // V^T [b][a][s]
__device__ __align__(16) __nv_bfloat16 g_Vtlo[BATCH * ADIM * SEQ];
__device__ __align__(16) float         g_P  [(size_t)BATCH * SEQ * SEQ];
__device__ __align__(16) __nv_bfloat16 g_Phi[(size_t)BATCH * SEQ * SEQ];
__device__ __align__(16) __nv_bfloat16 g_Plo[(size_t)BATCH * SEQ * SEQ];

// ---------------------------------------------------------------------------
// PTX helpers (no sm_103a-only features: mma.sync / ldmatrix / cp.async only)
// ---------------------------------------------------------------------------
__device__ __forceinline__ uint32_t smem_to_u32(const void* p) {
    uint32_t a;
    asm("{ .reg .u64 t; cvta.to.shared.u64 t, %1; cvt.u32.u64 %0, t; }"
        : "=r"(a) : "l"(p));
    return a;
}

__device__ __forceinline__ void cp16(uint32_t dst, const void* src) {
    asm volatile("cp.async.cg.shared.global [%0], [%1], 16;"
                 :: "r"(dst), "l"(src) : "memory");
}

__device__ __forceinline__ void ldsm_x4(uint32_t (&r)[4], uint32_t addr) {
    asm volatile("ldmatrix.sync.aligned.m8n8.x4.shared.b16 {%0,%1,%2,%3}, [%4];"
                 : "=r"(r[0]), "=r"(r[1]), "=r"(r[2]), "=r"(r[3]) : "r"(addr));
}

__device__ __forceinline__ void mma_bf16(float (&c)[4], const uint32_t (&a)[4],
                                         const uint32_t* b) {
    asm volatile(
        "mma.sync.aligned.m16n8k16.row.col.f32.bf16.bf16.f32 "
        "{%0,%1,%2,%3}, {%4,%5,%6,%7}, {%8,%9}, {%0,%1,%2,%3};"
        : "+f"(c[0]), "+f"(c[1]), "+f"(c[2]), "+f"(c[3])
        : "r"(a[0]), "r"(a[1]), "r"(a[2]), "r"(a[3]), "r"(b[0]), "r"(b[1]));
}

// ---------------------------------------------------------------------------
// SMEM: 2 stages x 4 tiles (A_hi, A_lo, B_hi, B_lo), each 128 rows x 128B SW128
// ---------------------------------------------------------------------------
#define TILE_BYTES  16384
#define STAGE_BYTES 65536
#define SMEM_BYTES  131072

__device__ __forceinline__ uint32_t sw128(uint32_t off) {
    return off ^ ((off >> 3) & 0x70);
}

// Prefetch one 64-wide K chunk of all 4 operand tiles into `stage`.
__device__ __forceinline__ void prefetch_chunk(
    uint32_t smem_u32, int stage, int kt,
    const __nv_bfloat16* __restrict__ a_hi, const __nv_bfloat16* __restrict__ a_lo, int lda,
    const __nv_bfloat16* __restrict__ b_hi, const __nv_bfloat16* __restrict__ b_lo, int ldb,
    int tid)
{
    #pragma unroll
    for (int arr = 0; arr < 4; ++arr) {
        const __nv_bfloat16* src =
            arr == 0 ? a_hi : arr == 1 ? a_lo : arr == 2 ? b_hi : b_lo;
        const int ld = arr < 2 ? lda : ldb;
        const uint32_t tbase = smem_u32 + stage * STAGE_BYTES + arr * TILE_BYTES;
        #pragma unroll
        for (int ii = 0; ii < 4; ++ii) {
            const int rem = ii * 256 + tid;            // [0, 1024)
            const int row = rem >> 3, seg = rem & 7;   // 128 rows x 8 x 16B
            const __nv_bfloat16* g = src + (size_t)row * ld + kt + seg * 8;
            cp16(tbase + sw128((uint32_t)(row * 128 + seg * 16)), g);
        }
    }
    asm volatile("cp.async.commit_group;" ::: "memory");
}

// Compute one 64-wide K chunk from `stage`.  Warp tile 64x32; bf16x3.
__device__ __forceinline__ void compute_chunk(
    uint32_t smem_u32, int stage, int wm, int wn, int lane, float acc[4][4][4])
{
    const uint32_t st = smem_u32 + stage * STAGE_BYTES;
    #pragma unroll
    for (int ks = 0; ks < 4; ++ks) {
        uint32_t ah[4][4], al[4][4], bh[2][4], bl[2][4];
        #pragma unroll
        for (int mt = 0; mt < 4; ++mt) {
            const int row = wm + mt * 16 + (lane & 15);
            const int byt = ks * 32 + ((lane >> 4) << 4);
            const uint32_t sw = sw128((uint32_t)(row * 128 + byt));
            ldsm_x4(ah[mt], st + sw);
            ldsm_x4(al[mt], st + TILE_BYTES + sw);
        }
        #pragma unroll
        for (int p = 0; p < 2; ++p) {
            const int row = wn + p * 16 + ((lane >> 4) << 3) + (lane & 7);
            const int byt = ks * 32 + (((lane >> 3) & 1) << 4);
            const uint32_t sw = sw128((uint32_t)(row * 128 + byt));
            ldsm_x4(bh[p], st + 2 * TILE_BYTES + sw);
            ldsm_x4(bl[p], st + 3 * TILE_BYTES + sw);
        }
        #pragma unroll
        for (int mt = 0; mt < 4; ++mt)
            #pragma unroll
            for (int nt = 0; nt < 4; ++nt) {
                const uint32_t* bhr = &bh[nt >> 1][(nt & 1) * 2];
                const uint32_t* blr = &bl[nt >> 1][(nt & 1) * 2];
                mma_bf16(acc[mt][nt], ah[mt], bhr);   // hi*hi
                mma_bf16(acc[mt][nt], al[mt], bhr);   // lo*hi
                mma_bf16(acc[mt][nt], ah[mt], blr);   // hi*lo
            }
    }
}

// D(128x128) = (Ahi+Alo)(128xK) . (Bhi+Blo)(128xK)^T,  klen multiple of 64.
__device__ __forceinline__ void mma_mainloop(
    uint32_t smem_u32,
    const __nv_bfloat16* __restrict__ a_hi, const __nv_bfloat16* __restrict__ a_lo, int lda,
    const __nv_bfloat16* __restrict__ b_hi, const __nv_bfloat16* __restrict__ b_lo, int ldb,
    int klen, float acc[4][4][4])
{
    const int tid = threadIdx.x;
    const int lane = tid & 31, w = tid >> 5;
    const int wm = (w & 1) * 64, wn = (w >> 1) * 32;
    const int nch = klen >> 6;

    prefetch_chunk(smem_u32, 0, 0, a_hi, a_lo, lda, b_hi, b_lo, ldb, tid);

    for (int ch = 0; ch < nch; ++ch) {
        if (ch + 1 < nch) {
            prefetch_chunk(smem_u32, (ch + 1) & 1, (ch + 1) << 6,
                           a_hi, a_lo, lda, b_hi, b_lo, ldb, tid);
            asm volatile("cp.async.wait_group 1;" ::: "memory");
        } else {
            asm volatile("cp.async.wait_group 0;" ::: "memory");
        }
        __syncthreads();
        compute_chunk(smem_u32, ch & 1, wm, wn, lane, acc);
        __syncthreads();
    }
}

// ---------------------------------------------------------------------------
// Split fp32 -> bf16 hi/lo.  which: 0=X, 1..3=W_{k,q,v}
// ---------------------------------------------------------------------------
__global__ __launch_bounds__(256) void k_split(const float* __restrict__ src, int which) {
    __nv_bfloat16 *hi, *lo;
    if (which == 0) { hi = g_Xhi; lo = g_Xlo; }
    else { hi = g_Whi + (size_t)(which - 1) * ADIM * EMB;
           lo = g_Wlo + (size_t)(which - 1) * ADIM * EMB; }
    const int i = (blockIdx.x * 256 + threadIdx.x) * 4;
    float4 v = *(const float4*)(src + i);
    float vv[4] = {v.x, v.y, v.z, v.w};
    __nv_bfloat16 h[4], l[4];
    #pragma unroll
    for (int j = 0; j < 4; ++j) {
        h[j] = __float2bfloat16(vv[j]);
        l[j] = __float2bfloat16(vv[j] - __bfloat162float(h[j]));
    }
    __nv_bfloat162 h01, h23, l01, l23;
    h01.x = h[0]; h01.y = h[1]; h23.x = h[2]; h23.y = h[3];
    l01.x = l[0]; l01.y = l[1]; l23.x = l[2]; l23.y = l[3];
    *(__nv_bfloat162*)(hi + i)     = h01;
    *(__nv_bfloat162*)(hi + i + 2) = h23;
    *(__nv_bfloat162*)(lo + i)     = l01;
    *(__nv_bfloat162*)(lo + i + 2) = l23;
}

// ---------------------------------------------------------------------------
// QKV projection: C = X @ W^T, z selects {K,Q,V}. V stored transposed + split.
// ---------------------------------------------------------------------------
__global__ __launch_bounds__(256, 1) void k_qkv() {
    extern __shared__ char smem[];
    const int bn = blockIdx.x * 128;
    const int bm = blockIdx.y * 128;
    const int z  = blockIdx.z;
    const uint32_t smem_u32 = smem_to_u32(smem);

    float acc[4][4][4] = {};
    const __nv_bfloat16* Wh = g_Whi + (size_t)z * ADIM * EMB + (size_t)bn * EMB;
    const __nv_bfloat16* Wl = g_Wlo + (size_t)z * ADIM * EMB + (size_t)bn * EMB;
    mma_mainloop(smem_u32,
                 g_Xhi + (size_t)bm * EMB, g_Xlo + (size_t)bm * EMB, EMB,
                 Wh, Wl, EMB, EMB, acc);

    const int lane = threadIdx.x & 31, w = threadIdx.x >> 5;
    const int wm = (w & 1) * 64, wn = (w >> 1) * 32;
    const int gid = lane >> 2, tq = lane & 3;

    #pragma unroll
    for (int mt = 0; mt < 4; ++mt)
        #pragma unroll
        for (int nt = 0; nt < 4; ++nt) {
            const int c = bn + wn + nt * 8 + tq * 2;
            #pragma unroll
            for (int half = 0; half < 2; ++half) {
                const int r = bm + wm + mt * 16 + gid + half * 8;
                const float v0 = acc[mt][nt][half * 2];
                const float v1 = acc[mt][nt][half * 2 + 1];
                __nv_bfloat16 h0 = __float2bfloat16(v0), h1 = __float2bfloat16(v1);
                __nv_bfloat16 l0 = __float2bfloat16(v0 - __bfloat162float(h0));
                __nv_bfloat16 l1 = __float2bfloat16(v1 - __bfloat162float(h1));
                if (z == 2) {
                    const int b = r >> 11, s = r & 2047;
                    const size_t base = ((size_t)b << 21) + s;
                    g_Vthi[base + (size_t)c * SEQ]       = h0;
                    g_Vthi[base + (size_t)(c + 1) * SEQ] = h1;
                    g_Vtlo[base + (size_t)c * SEQ]       = l0;
                    g_Vtlo[base + (size_t)(c + 1) * SEQ] = l1;
                } else {
                    __nv_bfloat16* Oh = (z == 0) ? g_Khi : g_Qhi;
                    __nv_bfloat16* Ol = (z == 0) ? g_Klo : g_Qlo;
                    __nv_bfloat162 hh, ll;
                    hh.x = h0; hh.y = h1; ll.x = l0; ll.y = l1;
                    *(__nv_bfloat162*)(Oh + (size_t)r * ADIM + c) = hh;
                    *(__nv_bfloat162*)(Ol + (size_t)r * ADIM + c) = ll;
                }
            }
        }
}

// ---------------------------------------------------------------------------
// Scores: P[b,q,k] = (Q . K) * scale for k<=q (fp32); tiles above diag skipped.
// ---------------------------------------------------------------------------
__global__ __launch_bounds__(256, 1) void k_scores() {
    const int bk = blockIdx.x * 128;
    const int bq = blockIdx.y * 128;
    const int b  = blockIdx.z;
    if (bk > bq) return;

    extern __shared__ char smem[];
    const uint32_t smem_u32 = smem_to_u32(smem);

    float acc[4][4][4] = {};
    const size_t qo = ((size_t)b * SEQ + bq) * ADIM;
    const size_t ko = ((size_t)b * SEQ + bk) * ADIM;
    mma_mainloop(smem_u32,
                 g_Qhi + qo, g_Qlo + qo, ADIM,
                 g_Khi + ko, g_Klo + ko, ADIM, ADIM, acc);

    const float scale = 0.03125f;  // 1/sqrt(1024)
    const int lane = threadIdx.x & 31, w = threadIdx.x >> 5;
    const int wm = (w & 1) * 64, wn = (w >> 1) * 32;
    const int gid = lane >> 2, tq = lane & 3;
    float* Pb = g_P + (size_t)b * SEQ * SEQ;

    #pragma unroll
    for (int mt = 0; mt < 4; ++mt)
        #pragma unroll
        for (int nt = 0; nt < 4; ++nt) {
            const int k = bk + wn + nt * 8 + tq * 2;
            #pragma unroll
            for (int half = 0; half < 2; ++half) {
                const int q = bq + wm + mt * 16 + gid + half * 8;
                const float v0 = acc[mt][nt][half * 2] * scale;
                const float v1 = acc[mt][nt][half * 2 + 1] * scale;
                float* prow = Pb + (size_t)q * SEQ;
                if (bk < bq) {
                    *(float2*)(prow + k) = make_float2(v0, v1);
                } else {
                    if (k     <= q) prow[k]     = v0;
                    if (k + 1 <= q) prow[k + 1] = v1;
                }
            }
        }
}

// ---------------------------------------------------------------------------
// Softmax over k in [0,q]; writes bf16 hi/lo, zero-fills (q, 128-tile end).
// ---------------------------------------------------------------------------
__global__ __launch_bounds__(256) void k_softmax() {
    const int row = blockIdx.x;
    const int b = row / SEQ, q = row % SEQ;
    const size_t off = ((size_t)b * SEQ + q) * SEQ;
    const float* p = g_P + off;
    const int n = q + 1;

    const int tid = threadIdx.x, lane = tid & 31, wid = tid >> 5;
    __shared__ float red[8];

    float m = -CUDART_INF_F;
    for (int k = tid; k < n; k += 256) m = fmaxf(m, p[k]);
    #pragma unroll
    for (int o = 16; o > 0; o >>= 1) m = fmaxf(m, __shfl_xor_sync(0xffffffffu, m, o));
    if (lane == 0) red[wid] = m;
    __syncthreads();
    float rowmax = red[0];
    #pragma unroll
    for (int i = 1; i < 8; ++i) rowmax = fmaxf(rowmax, red[i]);
    __syncthreads();

    float s = 0.0f;
    for (int k = tid; k < n; k += 256) s += expf(p[k] - rowmax);
    #pragma unroll
    for (int o = 16; o > 0; o >>= 1) s += __shfl_xor_sync(0xffffffffu, s, o);
    if (lane == 0) red[wid] = s;
    __syncthreads();
    float rowsum = 0.0f;
    #pragma unroll
    for (int i = 0; i < 8; ++i) rowsum += red[i];
    const float inv = 1.0f / rowsum;

    __nv_bfloat16* ph = g_Phi + off;
    __nv_bfloat16* pl = g_Plo + off;
    for (int k = tid; k < n; k += 256) {
        float wgt = expf(p[k] - rowmax) * inv;
        __nv_bfloat16 hi = __float2bfloat16(wgt);
        ph[k] = hi;
        pl[k] = __float2bfloat16(wgt - __bfloat162float(hi));
    }
    const int kend = (q & ~127) + 128;
    const __nv_bfloat16 z = __float2bfloat16(0.0f);
    for (int k = n + tid; k < kend; k += 256) { ph[k] = z; pl[k] = z; }
}

// ---------------------------------------------------------------------------
// AV: out = P @ V (via V^T), K-loop clipped to q-tile end. Round 4 decimals.
// ---------------------------------------------------------------------------
__global__ __launch_bounds__(256, 1) void k_av(float* __restrict__ out) {
    const int bn = blockIdx.x * 128;
    const int bm = blockIdx.y * 128;
    const int b  = blockIdx.z;

    extern __shared__ char smem[];
    const uint32_t smem_u32 = smem_to_u32(smem);

    float acc[4][4][4] = {};
    const size_t po = ((size_t)b * SEQ + bm) * SEQ;
    const size_t vo = ((size_t)b << 21) + (size_t)bn * SEQ;
    mma_mainloop(smem_u32,
                 g_Phi + po, g_Plo + po, SEQ,
                 g_Vthi + vo, g_Vtlo + vo, SEQ, bm + 128, acc);

    const int lane = threadIdx.x & 31, w = threadIdx.x >> 5;
    const int wm = (w & 1) * 64, wn = (w >> 1) * 32;
    const int gid = lane >> 2, tq = lane & 3;

    #pragma unroll
    for (int mt = 0; mt < 4; ++mt)
        #pragma unroll
        for (int nt = 0; nt < 4; ++nt) {
            const int c = bn + wn + nt * 8 + tq * 2;
            #pragma unroll
            for (int half = 0; half < 2; ++half) {
                const int q = bm + wm + mt * 16 + gid + half * 8;
                const float v0 = rintf(acc[mt][nt][half * 2]     * 1.0e4f) * 1.0e-4f;
                const float v1 = rintf(acc[mt][nt][half * 2 + 1] * 1.0e4f) * 1.0e-4f;
                *(float2*)(out + ((size_t)b * SEQ + q) * ADIM + c) = make_float2(v0, v1);
            }
        }
}

// ---------------------------------------------------------------------------
extern "C" void kernel_launch(void* const* d_in, const int* in_sizes, int n_in,
                              void* d_out, int out_size)
{
    const float* X  = (const float*)d_in[0];
    const float* Wk = (const float*)d_in[1];
    const float* Wq = (const float*)d_in[2];
    const float* Wv = (const float*)d_in[3];
    float* out = (float*)d_out;

    cudaFuncSetAttribute(k_qkv,    cudaFuncAttributeMaxDynamicSharedMemorySize, SMEM_BYTES);
    cudaFuncSetAttribute(k_scores, cudaFuncAttributeMaxDynamicSharedMemorySize, SMEM_BYTES);
    cudaFuncSetAttribute(k_av,     cudaFuncAttributeMaxDynamicSharedMemorySize, SMEM_BYTES);

    k_split<<<BSEQ * EMB / 1024, 256>>>(X, 0);
    k_split<<<ADIM * EMB / 1024, 256>>>(Wk, 1);
    k_split<<<ADIM * EMB / 1024, 256>>>(Wq, 2);
    k_split<<<ADIM * EMB / 1024, 256>>>(Wv, 3);

    k_qkv<<<dim3(ADIM / 128, BSEQ / 128, 3), 256, SMEM_BYTES>>>();
    k_scores<<<dim3(SEQ / 128, SEQ / 128, BATCH), 256, SMEM_BYTES>>>();
    k_softmax<<<BSEQ, 256>>>();
    k_av<<<dim3(ADIM / 128, SEQ / 128, BATCH), 256, SMEM_BYTES>>>(out);
}

// round 4
// speedup vs baseline: 3.2887x; 1.0232x over previous
#include <cuda_runtime.h>
#include <cuda_bf16.h>
#include <math_constants.h>
#include <cstdint>

#define BATCH 4
#define SEQ   2048
#define EMB   1024
#define ADIM  1024
#define BSEQ  (BATCH * SEQ)

// ---------------------------------------------------------------------------
// Scratch (__device__ globals per allocation-free rule)
// ---------------------------------------------------------------------------
__device__ __align__(16) __nv_bfloat16 g_Xhi[BSEQ * EMB];
__device__ __align__(16) __nv_bfloat16 g_Xlo[BSEQ * EMB];
__device__ __align__(16) __nv_bfloat16 g_Whi[3 * ADIM * EMB];
__device__ __align__(16) __nv_bfloat16 g_Wlo[3 * ADIM * EMB];
__device__ __align__(16) __nv_bfloat16 g_Qhi[BSEQ * ADIM];
__device__ __align__(16) __nv_bfloat16 g_Qlo[BSEQ * ADIM];
__device__ __align__(16) __nv_bfloat16 g_Khi[BSEQ * ADIM];
__device__ __align__(16) __nv_bfloat16 g_Klo[BSEQ * ADIM];
__device__ __align__(16) __nv_bfloat16 g_Vthi[BATCH * ADIM * SEQ];  // V^T [b][a][s]
__device__ __align__(16) __nv_bfloat16 g_Vtlo[BATCH * ADIM * SEQ];
__device__ __align__(16) float         g_P  [(size_t)BATCH * SEQ * SEQ];
__device__ __align__(16) __nv_bfloat16 g_Phi[(size_t)BATCH * SEQ * SEQ];
__device__ __align__(16) __nv_bfloat16 g_Plo[(size_t)BATCH * SEQ * SEQ];

// ---------------------------------------------------------------------------
// PTX helpers (sm_90-safe subset: mma.sync / ldmatrix / cp.async)
// ---------------------------------------------------------------------------
__device__ __forceinline__ uint32_t smem_to_u32(const void* p) {
    uint32_t a;
    asm("{ .reg .u64 t; cvta.to.shared.u64 t, %1; cvt.u32.u64 %0, t; }"
        : "=r"(a) : "l"(p));
    return a;
}

__device__ __forceinline__ void cp16(uint32_t dst, const void* src) {
    asm volatile("cp.async.cg.shared.global [%0], [%1], 16;"
                 :: "r"(dst), "l"(src) : "memory");
}

__device__ __forceinline__ void ldsm_x4(uint32_t (&r)[4], uint32_t addr) {
    asm volatile("ldmatrix.sync.aligned.m8n8.x4.shared.b16 {%0,%1,%2,%3}, [%4];"
                 : "=r"(r[0]), "=r"(r[1]), "=r"(r[2]), "=r"(r[3]) : "r"(addr));
}

__device__ __forceinline__ void mma_bf16(float (&c)[4], const uint32_t (&a)[4],
                                         const uint32_t* b) {
    asm volatile(
        "mma.sync.aligned.m16n8k16.row.col.f32.bf16.bf16.f32 "
        "{%0,%1,%2,%3}, {%4,%5,%6,%7}, {%8,%9}, {%0,%1,%2,%3};"
        : "+f"(c[0]), "+f"(c[1]), "+f"(c[2]), "+f"(c[3])
        : "r"(a[0]), "r"(a[1]), "r"(a[2]), "r"(a[3]), "r"(b[0]), "r"(b[1]));
}

// ---------------------------------------------------------------------------
// SMEM: 3 stages x 4 tiles (A_hi, A_lo, B_hi, B_lo), 128 rows x 128B, SW128
// ---------------------------------------------------------------------------
#define TILE_BYTES  16384
#define STAGE_BYTES 65536
#define SMEM_BYTES  196608
#define TSTRIDE     136            // padded bf16 row stride for epilogue staging

__device__ __forceinline__ uint32_t sw128(uint32_t off) {
    return off ^ ((off >> 3) & 0x70);
}

__device__ __forceinline__ void prefetch_chunk(
    uint32_t smem_u32, int stage, int kt,
    const __nv_bfloat16* __restrict__ a_hi, const __nv_bfloat16* __restrict__ a_lo, int lda,
    const __nv_bfloat16* __restrict__ b_hi, const __nv_bfloat16* __restrict__ b_lo, int ldb,
    int tid)
{
    #pragma unroll
    for (int arr = 0; arr < 4; ++arr) {
        const __nv_bfloat16* src =
            arr == 0 ? a_hi : arr == 1 ? a_lo : arr == 2 ? b_hi : b_lo;
        const int ld = arr < 2 ? lda : ldb;
        const uint32_t tbase = smem_u32 + stage * STAGE_BYTES + arr * TILE_BYTES;
        #pragma unroll
        for (int ii = 0; ii < 4; ++ii) {
            const int rem = ii * 256 + tid;            // [0, 1024)
            const int row = rem >> 3, seg = rem & 7;   // 128 rows x 8 x 16B
            const __nv_bfloat16* g = src + (size_t)row * ld + kt + seg * 8;
            cp16(tbase + sw128((uint32_t)(row * 128 + seg * 16)), g);
        }
    }
    asm volatile("cp.async.commit_group;" ::: "memory");
}

// One 64-wide K chunk.  Warp tile 64x32; bf16x3 with term-major ordering.
__device__ __forceinline__ void compute_chunk(
    uint32_t smem_u32, int stage, int wm, int wn, int lane, float acc[4][4][4])
{
    const uint32_t st = smem_u32 + stage * STAGE_BYTES;
    #pragma unroll
    for (int ks = 0; ks < 4; ++ks) {
        uint32_t ah[4][4], al[4][4], bh[2][4], bl[2][4];
        #pragma unroll
        for (int mt = 0; mt < 4; ++mt) {
            const int row = wm + mt * 16 + (lane & 15);
            const int byt = ks * 32 + ((lane >> 4) << 4);
            const uint32_t sw = sw128((uint32_t)(row * 128 + byt));
            ldsm_x4(ah[mt], st + sw);
            ldsm_x4(al[mt], st + TILE_BYTES + sw);
        }
        #pragma unroll
        for (int p = 0; p < 2; ++p) {
            const int row = wn + p * 16 + ((lane >> 4) << 3) + (lane & 7);
            const int byt = ks * 32 + (((lane >> 3) & 1) << 4);
            const uint32_t sw = sw128((uint32_t)(row * 128 + byt));
            ldsm_x4(bh[p], st + 2 * TILE_BYTES + sw);
            ldsm_x4(bl[p], st + 3 * TILE_BYTES + sw);
        }
        // term-major: maximize reuse distance on each accumulator
        #pragma unroll
        for (int mt = 0; mt < 4; ++mt)
            #pragma unroll
            for (int nt = 0; nt < 4; ++nt)
                mma_bf16(acc[mt][nt], ah[mt], &bh[nt >> 1][(nt & 1) * 2]);
        #pragma unroll
        for (int mt = 0; mt < 4; ++mt)
            #pragma unroll
            for (int nt = 0; nt < 4; ++nt)
                mma_bf16(acc[mt][nt], al[mt], &bh[nt >> 1][(nt & 1) * 2]);
        #pragma unroll
        for (int mt = 0; mt < 4; ++mt)
            #pragma unroll
            for (int nt = 0; nt < 4; ++nt)
                mma_bf16(acc[mt][nt], ah[mt], &bl[nt >> 1][(nt & 1) * 2]);
    }
}

// D(128x128) = (Ahi+Alo)(128xK) . (Bhi+Blo)(128xK)^T,  klen multiple of 64.
// 3-stage cp.async pipeline, ONE barrier per chunk.
__device__ __forceinline__ void mma_mainloop(
    uint32_t smem_u32,
    const __nv_bfloat16* __restrict__ a_hi, const __nv_bfloat16* __restrict__ a_lo, int lda,
    const __nv_bfloat16* __restrict__ b_hi, const __nv_bfloat16* __restrict__ b_lo, int ldb,
    int klen, float acc[4][4][4])
{
    const int tid = threadIdx.x;
    const int lane = tid & 31, w = tid >> 5;
    const int wm = (w & 1) * 64, wn = (w >> 1) * 32;
    const int nch = klen >> 6;

    prefetch_chunk(smem_u32, 0, 0, a_hi, a_lo, lda, b_hi, b_lo, ldb, tid);

    int st = 0, nst = 1;
    for (int ch = 0; ch < nch; ++ch) {
        if (ch + 1 < nch) {
            // stage nst held chunk ch-2; everyone passed the previous barrier
            // AFTER finishing compute(ch-2)  ->  safe to overwrite.
            prefetch_chunk(smem_u32, nst, (ch + 1) << 6,
                           a_hi, a_lo, lda, b_hi, b_lo, ldb, tid);
            asm volatile("cp.async.wait_group 1;" ::: "memory");
        } else {
            asm volatile("cp.async.wait_group 0;" ::: "memory");
        }
        __syncthreads();
        compute_chunk(smem_u32, st, wm, wn, lane, acc);
        st = nst; nst = nst + 1 == 3 ? 0 : nst + 1;
    }
    __syncthreads();   // epilogue reuses smem
}

// ---------------------------------------------------------------------------
// Splits fp32 -> bf16 hi/lo
// ---------------------------------------------------------------------------
__device__ __forceinline__ void split4(const float* src, __nv_bfloat16* hi,
                                       __nv_bfloat16* lo, int i) {
    float4 v = *(const float4*)(src + i);
    float vv[4] = {v.x, v.y, v.z, v.w};
    __nv_bfloat16 h[4], l[4];
    #pragma unroll
    for (int j = 0; j < 4; ++j) {
        h[j] = __float2bfloat16(vv[j]);
        l[j] = __float2bfloat16(vv[j] - __bfloat162float(h[j]));
    }
    __nv_bfloat162 h01, h23, l01, l23;
    h01.x = h[0]; h01.y = h[1]; h23.x = h[2]; h23.y = h[3];
    l01.x = l[0]; l01.y = l[1]; l23.x = l[2]; l23.y = l[3];
    *(__nv_bfloat162*)(hi + i)     = h01;
    *(__nv_bfloat162*)(hi + i + 2) = h23;
    *(__nv_bfloat162*)(lo + i)     = l01;
    *(__nv_bfloat162*)(lo + i + 2) = l23;
}

__global__ __launch_bounds__(256) void k_splitX(const float* __restrict__ src) {
    split4(src, g_Xhi, g_Xlo, (blockIdx.x * 256 + threadIdx.x) * 4);
}

__global__ __launch_bounds__(256) void k_splitW(const float* __restrict__ w0,
                                                const float* __restrict__ w1,
                                                const float* __restrict__ w2) {
    const int z = blockIdx.y;
    const float* src = z == 0 ? w0 : z == 1 ? w1 : w2;
    split4(src, g_Whi + (size_t)z * ADIM * EMB, g_Wlo + (size_t)z * ADIM * EMB,
           (blockIdx.x * 256 + threadIdx.x) * 4);
}

// ---------------------------------------------------------------------------
// QKV projection: C = X @ W^T, z selects {K,Q,V}.
// Epilogue stages tile in smem: Q/K row-major, V transposed; coalesced uint4 out.
// ---------------------------------------------------------------------------
__global__ __launch_bounds__(256, 1) void k_qkv() {
    extern __shared__ char smem[];
    const int bn = blockIdx.x * 128;
    const int bm = blockIdx.y * 128;
    const int z  = blockIdx.z;
    const uint32_t smem_u32 = smem_to_u32(smem);

    float acc[4][4][4] = {};
    const __nv_bfloat16* Wh = g_Whi + (size_t)z * ADIM * EMB + (size_t)bn * EMB;
    const __nv_bfloat16* Wl = g_Wlo + (size_t)z * ADIM * EMB + (size_t)bn * EMB;
    mma_mainloop(smem_u32,
                 g_Xhi + (size_t)bm * EMB, g_Xlo + (size_t)bm * EMB, EMB,
                 Wh, Wl, EMB, EMB, acc);

    const int tid = threadIdx.x, lane = tid & 31, w = tid >> 5;
    const int wm = (w & 1) * 64, wn = (w >> 1) * 32;
    const int gid = lane >> 2, tq = lane & 3;

    __nv_bfloat16* Th = (__nv_bfloat16*)smem;          // [128][TSTRIDE]
    __nv_bfloat16* Tl = Th + 128 * TSTRIDE;

    #pragma unroll
    for (int mt = 0; mt < 4; ++mt)
        #pragma unroll
        for (int nt = 0; nt < 4; ++nt) {
            const int cl = wn + nt * 8 + tq * 2;
            #pragma unroll
            for (int half = 0; half < 2; ++half) {
                const int rl = wm + mt * 16 + gid + half * 8;
                const float v0 = acc[mt][nt][half * 2];
                const float v1 = acc[mt][nt][half * 2 + 1];
                __nv_bfloat16 h0 = __float2bfloat16(v0), h1 = __float2bfloat16(v1);
                __nv_bfloat16 l0 = __float2bfloat16(v0 - __bfloat162float(h0));
                __nv_bfloat16 l1 = __float2bfloat16(v1 - __bfloat162float(h1));
                if (z == 2) {    // transpose: T[a][s]
                    Th[(cl)     * TSTRIDE + rl] = h0;
                    Th[(cl + 1) * TSTRIDE + rl] = h1;
                    Tl[(cl)     * TSTRIDE + rl] = l0;
                    Tl[(cl + 1) * TSTRIDE + rl] = l1;
                } else {         // row-major: T[s][a]
                    __nv_bfloat162 hh, ll;
                    hh.x = h0; hh.y = h1; ll.x = l0; ll.y = l1;
                    *(__nv_bfloat162*)(Th + rl * TSTRIDE + cl) = hh;
                    *(__nv_bfloat162*)(Tl + rl * TSTRIDE + cl) = ll;
                }
            }
        }
    __syncthreads();

    const int i = tid >> 1, hf = tid & 1;
    const uint4* sh = (const uint4*)(Th + i * TSTRIDE + hf * 64);
    const uint4* sl = (const uint4*)(Tl + i * TSTRIDE + hf * 64);
    __nv_bfloat16 *dh, *dl;
    if (z == 2) {
        const int b = bm >> 11, s0 = bm & 2047;
        const size_t base = ((size_t)b << 21) + (size_t)(bn + i) * SEQ + s0 + hf * 64;
        dh = g_Vthi + base; dl = g_Vtlo + base;
    } else {
        __nv_bfloat16* Oh = (z == 0) ? g_Khi : g_Qhi;
        __nv_bfloat16* Ol = (z == 0) ? g_Klo : g_Qlo;
        const size_t base = (size_t)(bm + i) * ADIM + bn + hf * 64;
        dh = Oh + base; dl = Ol + base;
    }
    #pragma unroll
    for (int j = 0; j < 8; ++j) ((uint4*)dh)[j] = sh[j];
    #pragma unroll
    for (int j = 0; j < 8; ++j) ((uint4*)dl)[j] = sl[j];
}

// ---------------------------------------------------------------------------
// Scores: P[b,q,k] = (Q . K) * scale for k<=q (fp32); above-diag tiles skipped.
// ---------------------------------------------------------------------------
__global__ __launch_bounds__(256, 1) void k_scores() {
    const int bk = blockIdx.x * 128;
    const int bq = blockIdx.y * 128;
    const int b  = blockIdx.z;
    if (bk > bq) return;

    extern __shared__ char smem[];
    const uint32_t smem_u32 = smem_to_u32(smem);

    float acc[4][4][4] = {};
    const size_t qo = ((size_t)b * SEQ + bq) * ADIM;
    const size_t ko = ((size_t)b * SEQ + bk) * ADIM;
    mma_mainloop(smem_u32,
                 g_Qhi + qo, g_Qlo + qo, ADIM,
                 g_Khi + ko, g_Klo + ko, ADIM, ADIM, acc);

    const float scale = 0.03125f;  // 1/sqrt(1024)
    const int lane = threadIdx.x & 31, w = threadIdx.x >> 5;
    const int wm = (w & 1) * 64, wn = (w >> 1) * 32;
    const int gid = lane >> 2, tq = lane & 3;
    float* Pb = g_P + (size_t)b * SEQ * SEQ;

    #pragma unroll
    for (int mt = 0; mt < 4; ++mt)
        #pragma unroll
        for (int nt = 0; nt < 4; ++nt) {
            const int k = bk + wn + nt * 8 + tq * 2;
            #pragma unroll
            for (int half = 0; half < 2; ++half) {
                const int q = bq + wm + mt * 16 + gid + half * 8;
                const float v0 = acc[mt][nt][half * 2] * scale;
                const float v1 = acc[mt][nt][half * 2 + 1] * scale;
                float* prow = Pb + (size_t)q * SEQ;
                if (bk < bq) {
                    *(float2*)(prow + k) = make_float2(v0, v1);
                } else {
                    if (k     <= q) prow[k]     = v0;
                    if (k + 1 <= q) prow[k + 1] = v1;
                }
            }
        }
}

// ---------------------------------------------------------------------------
// Register softmax: one gmem read, one bf16 hi/lo write, one exp per element.
// ---------------------------------------------------------------------------
__global__ __launch_bounds__(256) void k_softmax() {
    const int row = blockIdx.x;
    const int b = row >> 11, q = row & 2047;
    const size_t off = ((size_t)b * SEQ + q) * SEQ;
    const float* p = g_P + off;
    const int n = q + 1;

    const int tid = threadIdx.x, lane = tid & 31, wid = tid >> 5;
    __shared__ float red[8];

    float v[8];
    #pragma unroll
    for (int j = 0; j < 8; ++j) {
        const int k = j * 256 + tid;
        v[j] = (k < n) ? p[k] : -CUDART_INF_F;
    }

    float m = v[0];
    #pragma unroll
    for (int j = 1; j < 8; ++j) m = fmaxf(m, v[j]);
    #pragma unroll
    for (int o = 16; o > 0; o >>= 1) m = fmaxf(m, __shfl_xor_sync(0xffffffffu, m, o));
    if (lane == 0) red[wid] = m;
    __syncthreads();
    float rowmax = red[0];
    #pragma unroll
    for (int i = 1; i < 8; ++i) rowmax = fmaxf(rowmax, red[i]);
    __syncthreads();

    float s = 0.0f;
    #pragma unroll
    for (int j = 0; j < 8; ++j) {
        const float e = __expf(v[j] - rowmax);   // exp(-inf)=0 for invalid lanes
        v[j] = e;
        s += e;
    }
    #pragma unroll
    for (int o = 16; o > 0; o >>= 1) s += __shfl_xor_sync(0xffffffffu, s, o);
    if (lane == 0) red[wid] = s;
    __syncthreads();
    float rowsum = 0.0f;
    #pragma unroll
    for (int i = 0; i < 8; ++i) rowsum += red[i];
    const float inv = 1.0f / rowsum;

    __nv_bfloat16* ph = g_Phi + off;
    __nv_bfloat16* pl = g_Plo + off;
    const int kend = (q & ~127) + 128;           // AV reads only up to here
    #pragma unroll
    for (int j = 0; j < 8; ++j) {
        const int k = j * 256 + tid;
        if (k < n) {
            const float wgt = v[j] * inv;
            const __nv_bfloat16 hi = __float2bfloat16(wgt);
            ph[k] = hi;
            pl[k] = __float2bfloat16(wgt - __bfloat162float(hi));
        } else if (k < kend) {
            ph[k] = __float2bfloat16(0.0f);
            pl[k] = __float2bfloat16(0.0f);
        }
    }
}

// ---------------------------------------------------------------------------
// AV: out = P @ V (via V^T), K-loop clipped to q-tile end. Round 4 decimals.
// ---------------------------------------------------------------------------
__global__ __launch_bounds__(256, 1) void k_av(float* __restrict__ out) {
    const int bn = blockIdx.x * 128;
    const int bm = blockIdx.y * 128;
    const int b  = blockIdx.z;

    extern __shared__ char smem[];
    const uint32_t smem_u32 = smem_to_u32(smem);

    float acc[4][4][4] = {};
    const size_t po = ((size_t)b * SEQ + bm) * SEQ;
    const size_t vo = ((size_t)b << 21) + (size_t)bn * SEQ;
    mma_mainloop(smem_u32,
                 g_Phi + po, g_Plo + po, SEQ,
                 g_Vthi + vo, g_Vtlo + vo, SEQ, bm + 128, acc);

    const int lane = threadIdx.x & 31, w = threadIdx.x >> 5;
    const int wm = (w & 1) * 64, wn = (w >> 1) * 32;
    const int gid = lane >> 2, tq = lane & 3;

    #pragma unroll
    for (int mt = 0; mt < 4; ++mt)
        #pragma unroll
        for (int nt = 0; nt < 4; ++nt) {
            const int c = bn + wn + nt * 8 + tq * 2;
            #pragma unroll
            for (int half = 0; half < 2; ++half) {
                const int q = bm + wm + mt * 16 + gid + half * 8;
                const float v0 = rintf(acc[mt][nt][half * 2]     * 1.0e4f) * 1.0e-4f;
                const float v1 = rintf(acc[mt][nt][half * 2 + 1] * 1.0e4f) * 1.0e-4f;
                *(float2*)(out + ((size_t)b * SEQ + q) * ADIM + c) = make_float2(v0, v1);
            }
        }
}

// ---------------------------------------------------------------------------
extern "C" void kernel_launch(void* const* d_in, const int* in_sizes, int n_in,
                              void* d_out, int out_size)
{
    const float* X  = (const float*)d_in[0];
    const float* Wk = (const float*)d_in[1];
    const float* Wq = (const float*)d_in[2];
    const float* Wv = (const float*)d_in[3];
    float* out = (float*)d_out;

    cudaFuncSetAttribute(k_qkv,    cudaFuncAttributeMaxDynamicSharedMemorySize, SMEM_BYTES);
    cudaFuncSetAttribute(k_scores, cudaFuncAttributeMaxDynamicSharedMemorySize, SMEM_BYTES);
    cudaFuncSetAttribute(k_av,     cudaFuncAttributeMaxDynamicSharedMemorySize, SMEM_BYTES);

    k_splitX<<<BSEQ * EMB / 1024, 256>>>(X);
    k_splitW<<<dim3(ADIM * EMB / 1024, 3), 256>>>(Wk, Wq, Wv);

    k_qkv<<<dim3(ADIM / 128, BSEQ / 128, 3), 256, SMEM_BYTES>>>();
    k_scores<<<dim3(SEQ / 128, SEQ / 128, BATCH), 256, SMEM_BYTES>>>();
    k_softmax<<<BSEQ, 256>>>();
    k_av<<<dim3(ADIM / 128, SEQ / 128, BATCH), 256, SMEM_BYTES>>>(out);
}

// round 5
// speedup vs baseline: 4.6850x; 1.4246x over previous
#include <cuda_runtime.h>
#include <cuda_fp16.h>
#include <math_constants.h>
#include <cstdint>

#define BATCH 4
#define SEQ   2048
#define EMB   1024
#define ADIM  1024
#define BSEQ  (BATCH * SEQ)

// ---------------------------------------------------------------------------
// Scratch (__device__ globals per allocation-free rule)
// A-operands split fp16 hi/lo; B-operands single fp16.
// ---------------------------------------------------------------------------
__device__ __align__(16) __half g_Xhi[BSEQ * EMB];
__device__ __align__(16) __half g_Xlo[BSEQ * EMB];
__device__ __align__(16) __half g_W  [3 * ADIM * EMB];
__device__ __align__(16) __half g_Qhi[BSEQ * ADIM];
__device__ __align__(16) __half g_Qlo[BSEQ * ADIM];
__device__ __align__(16) __half g_K  [BSEQ * ADIM];
__device__ __align__(16) __half g_Vt [BATCH * ADIM * SEQ];   // V^T [b][a][s]
__device__ __align__(16) float  g_P  [(size_t)BATCH * SEQ * SEQ];
__device__ __align__(16) __half g_Phi[(size_t)BATCH * SEQ * SEQ];
__device__ __align__(16) __half g_Plo[(size_t)BATCH * SEQ * SEQ];

// ---------------------------------------------------------------------------
// PTX helpers (sm_90-safe subset: mma.sync / ldmatrix / cp.async)
// ---------------------------------------------------------------------------
__device__ __forceinline__ uint32_t smem_to_u32(const void* p) {
    uint32_t a;
    asm("{ .reg .u64 t; cvta.to.shared.u64 t, %1; cvt.u32.u64 %0, t; }"
        : "=r"(a) : "l"(p));
    return a;
}

__device__ __forceinline__ void cp16(uint32_t dst, const void* src) {
    asm volatile("cp.async.cg.shared.global [%0], [%1], 16;"
                 :: "r"(dst), "l"(src) : "memory");
}

__device__ __forceinline__ void ldsm_x4(uint32_t (&r)[4], uint32_t addr) {
    asm volatile("ldmatrix.sync.aligned.m8n8.x4.shared.b16 {%0,%1,%2,%3}, [%4];"
                 : "=r"(r[0]), "=r"(r[1]), "=r"(r[2]), "=r"(r[3]) : "r"(addr));
}

__device__ __forceinline__ void mma_f16(float (&c)[4], const uint32_t (&a)[4],
                                        const uint32_t* b) {
    asm volatile(
        "mma.sync.aligned.m16n8k16.row.col.f32.f16.f16.f32 "
        "{%0,%1,%2,%3}, {%4,%5,%6,%7}, {%8,%9}, {%0,%1,%2,%3};"
        : "+f"(c[0]), "+f"(c[1]), "+f"(c[2]), "+f"(c[3])
        : "r"(a[0]), "r"(a[1]), "r"(a[2]), "r"(a[3]), "r"(b[0]), "r"(b[1]));
}

// ---------------------------------------------------------------------------
// SMEM: 3 stages x 3 tiles (A_hi, A_lo, B), each 128 rows x 128B, SW128
// ---------------------------------------------------------------------------
#define TILE_BYTES  16384
#define STAGE_BYTES 49152
#define SMEM_BYTES  147456
#define TSTRIDE     136           // padded fp16 row stride for epilogue staging

__device__ __forceinline__ uint32_t sw128(uint32_t off) {
    return off ^ ((off >> 3) & 0x70);
}

__device__ __forceinline__ void prefetch_chunk(
    uint32_t smem_u32, int stage, int kt,
    const __half* __restrict__ a_hi, const __half* __restrict__ a_lo, int lda,
    const __half* __restrict__ b, int ldb, int tid)
{
    #pragma unroll
    for (int arr = 0; arr < 3; ++arr) {
        const __half* src = arr == 0 ? a_hi : arr == 1 ? a_lo : b;
        const int ld = arr < 2 ? lda : ldb;
        const uint32_t tbase = smem_u32 + stage * STAGE_BYTES + arr * TILE_BYTES;
        #pragma unroll
        for (int ii = 0; ii < 4; ++ii) {
            const int rem = ii * 256 + tid;            // [0, 1024)
            const int row = rem >> 3, seg = rem & 7;   // 128 rows x 8 x 16B
            const __half* g = src + (size_t)row * ld + kt + seg * 8;
            cp16(tbase + sw128((uint32_t)(row * 128 + seg * 16)), g);
        }
    }
    asm volatile("cp.async.commit_group;" ::: "memory");
}

// One 64-wide K chunk.  Warp tile 64x32; fp16 2-term (hi.B + lo.B).
__device__ __forceinline__ void compute_chunk(
    uint32_t smem_u32, int stage, int wm, int wn, int lane, float acc[4][4][4])
{
    const uint32_t st = smem_u32 + stage * STAGE_BYTES;
    #pragma unroll
    for (int ks = 0; ks < 4; ++ks) {
        uint32_t ah[4][4], al[4][4], bh[2][4];
        #pragma unroll
        for (int mt = 0; mt < 4; ++mt) {
            const int row = wm + mt * 16 + (lane & 15);
            const int byt = ks * 32 + ((lane >> 4) << 4);
            const uint32_t sw = sw128((uint32_t)(row * 128 + byt));
            ldsm_x4(ah[mt], st + sw);
            ldsm_x4(al[mt], st + TILE_BYTES + sw);
        }
        #pragma unroll
        for (int p = 0; p < 2; ++p) {
            const int row = wn + p * 16 + ((lane >> 4) << 3) + (lane & 7);
            const int byt = ks * 32 + (((lane >> 3) & 1) << 4);
            const uint32_t sw = sw128((uint32_t)(row * 128 + byt));
            ldsm_x4(bh[p], st + 2 * TILE_BYTES + sw);
        }
        #pragma unroll
        for (int mt = 0; mt < 4; ++mt)
            #pragma unroll
            for (int nt = 0; nt < 4; ++nt)
                mma_f16(acc[mt][nt], ah[mt], &bh[nt >> 1][(nt & 1) * 2]);
        #pragma unroll
        for (int mt = 0; mt < 4; ++mt)
            #pragma unroll
            for (int nt = 0; nt < 4; ++nt)
                mma_f16(acc[mt][nt], al[mt], &bh[nt >> 1][(nt & 1) * 2]);
    }
}

// D(128x128) = (Ahi+Alo)(128xK) . B(128xK)^T,  klen multiple of 64.
// 3-stage cp.async pipeline, one barrier per chunk.
__device__ __forceinline__ void mma_mainloop(
    uint32_t smem_u32,
    const __half* __restrict__ a_hi, const __half* __restrict__ a_lo, int lda,
    const __half* __restrict__ b, int ldb, int klen, float acc[4][4][4])
{
    const int tid = threadIdx.x;
    const int lane = tid & 31, w = tid >> 5;
    const int wm = (w & 1) * 64, wn = (w >> 1) * 32;
    const int nch = klen >> 6;

    prefetch_chunk(smem_u32, 0, 0, a_hi, a_lo, lda, b, ldb, tid);

    int st = 0, nst = 1;
    for (int ch = 0; ch < nch; ++ch) {
        if (ch + 1 < nch) {
            prefetch_chunk(smem_u32, nst, (ch + 1) << 6, a_hi, a_lo, lda, b, ldb, tid);
            asm volatile("cp.async.wait_group 1;" ::: "memory");
        } else {
            asm volatile("cp.async.wait_group 0;" ::: "memory");
        }
        __syncthreads();
        compute_chunk(smem_u32, st, wm, wn, lane, acc);
        st = nst; nst = nst + 1 == 3 ? 0 : nst + 1;
    }
    __syncthreads();   // epilogue reuses smem
}

// ---------------------------------------------------------------------------
// Splits: X -> fp16 hi/lo;  W -> fp16 single
// ---------------------------------------------------------------------------
__global__ __launch_bounds__(256) void k_splitX(const float* __restrict__ src) {
    const int i = (blockIdx.x * 256 + threadIdx.x) * 4;
    float4 v = *(const float4*)(src + i);
    float vv[4] = {v.x, v.y, v.z, v.w};
    __half h[4], l[4];
    #pragma unroll
    for (int j = 0; j < 4; ++j) {
        h[j] = __float2half_rn(vv[j]);
        l[j] = __float2half_rn(vv[j] - __half2float(h[j]));
    }
    __half2 h01, h23, l01, l23;
    h01.x = h[0]; h01.y = h[1]; h23.x = h[2]; h23.y = h[3];
    l01.x = l[0]; l01.y = l[1]; l23.x = l[2]; l23.y = l[3];
    *(__half2*)(g_Xhi + i)     = h01;
    *(__half2*)(g_Xhi + i + 2) = h23;
    *(__half2*)(g_Xlo + i)     = l01;
    *(__half2*)(g_Xlo + i + 2) = l23;
}

__global__ __launch_bounds__(256) void k_splitW(const float* __restrict__ w0,
                                                const float* __restrict__ w1,
                                                const float* __restrict__ w2) {
    const int z = blockIdx.y;
    const float* src = z == 0 ? w0 : z == 1 ? w1 : w2;
    __half* dst = g_W + (size_t)z * ADIM * EMB;
    const int i = (blockIdx.x * 256 + threadIdx.x) * 4;
    float4 v = *(const float4*)(src + i);
    __half2 a, b;
    a.x = __float2half_rn(v.x); a.y = __float2half_rn(v.y);
    b.x = __float2half_rn(v.z); b.y = __float2half_rn(v.w);
    *(__half2*)(dst + i)     = a;
    *(__half2*)(dst + i + 2) = b;
}

// ---------------------------------------------------------------------------
// QKV projection: C = X @ W^T, z selects {K, Q, V}.
// K: fp16 single.  Q: fp16 hi/lo.  V: fp16 single, transposed.
// Epilogue stages in padded smem, coalesced uint4 out.
// ---------------------------------------------------------------------------
__global__ __launch_bounds__(256, 1) void k_qkv() {
    extern __shared__ char smem[];
    const int bn = blockIdx.x * 128;
    const int bm = blockIdx.y * 128;
    const int z  = blockIdx.z;
    const uint32_t smem_u32 = smem_to_u32(smem);

    float acc[4][4][4] = {};
    const __half* W = g_W + (size_t)z * ADIM * EMB + (size_t)bn * EMB;
    mma_mainloop(smem_u32,
                 g_Xhi + (size_t)bm * EMB, g_Xlo + (size_t)bm * EMB, EMB,
                 W, EMB, EMB, acc);

    const int tid = threadIdx.x, lane = tid & 31, w = tid >> 5;
    const int wm = (w & 1) * 64, wn = (w >> 1) * 32;
    const int gid = lane >> 2, tq = lane & 3;

    __half* Th = (__half*)smem;               // [128][TSTRIDE]
    __half* Tl = Th + 128 * TSTRIDE;          // used only for Q (z==1)

    #pragma unroll
    for (int mt = 0; mt < 4; ++mt)
        #pragma unroll
        for (int nt = 0; nt < 4; ++nt) {
            const int cl = wn + nt * 8 + tq * 2;
            #pragma unroll
            for (int half = 0; half < 2; ++half) {
                const int rl = wm + mt * 16 + gid + half * 8;
                const float v0 = acc[mt][nt][half * 2];
                const float v1 = acc[mt][nt][half * 2 + 1];
                const __half h0 = __float2half_rn(v0), h1 = __float2half_rn(v1);
                if (z == 2) {     // transpose: T[a][s]
                    Th[(cl)     * TSTRIDE + rl] = h0;
                    Th[(cl + 1) * TSTRIDE + rl] = h1;
                } else {
                    __half2 hh; hh.x = h0; hh.y = h1;
                    *(__half2*)(Th + rl * TSTRIDE + cl) = hh;
                    if (z == 1) {
                        __half2 ll;
                        ll.x = __float2half_rn(v0 - __half2float(h0));
                        ll.y = __float2half_rn(v1 - __half2float(h1));
                        *(__half2*)(Tl + rl * TSTRIDE + cl) = ll;
                    }
                }
            }
        }
    __syncthreads();

    const int i = tid >> 1, hf = tid & 1;
    const uint4* sh = (const uint4*)(Th + i * TSTRIDE + hf * 64);
    if (z == 2) {
        const int b = bm >> 11, s0 = bm & 2047;
        uint4* dh = (uint4*)(g_Vt + ((size_t)b << 21) + (size_t)(bn + i) * SEQ + s0 + hf * 64);
        #pragma unroll
        for (int j = 0; j < 8; ++j) dh[j] = sh[j];
    } else if (z == 0) {
        uint4* dh = (uint4*)(g_K + (size_t)(bm + i) * ADIM + bn + hf * 64);
        #pragma unroll
        for (int j = 0; j < 8; ++j) dh[j] = sh[j];
    } else {
        const uint4* sl = (const uint4*)(Tl + i * TSTRIDE + hf * 64);
        uint4* dh = (uint4*)(g_Qhi + (size_t)(bm + i) * ADIM + bn + hf * 64);
        uint4* dl = (uint4*)(g_Qlo + (size_t)(bm + i) * ADIM + bn + hf * 64);
        #pragma unroll
        for (int j = 0; j < 8; ++j) dh[j] = sh[j];
        #pragma unroll
        for (int j = 0; j < 8; ++j) dl[j] = sl[j];
    }
}

// ---------------------------------------------------------------------------
// Scores: P[b,q,k] = (Q . K) * scale for k<=q; above-diag tiles skipped.
// ---------------------------------------------------------------------------
__global__ __launch_bounds__(256, 1) void k_scores() {
    const int bk = blockIdx.x * 128;
    const int bq = blockIdx.y * 128;
    const int b  = blockIdx.z;
    if (bk > bq) return;

    extern __shared__ char smem[];
    const uint32_t smem_u32 = smem_to_u32(smem);

    float acc[4][4][4] = {};
    const size_t qo = ((size_t)b * SEQ + bq) * ADIM;
    const size_t ko = ((size_t)b * SEQ + bk) * ADIM;
    mma_mainloop(smem_u32, g_Qhi + qo, g_Qlo + qo, ADIM, g_K + ko, ADIM, ADIM, acc);

    const float scale = 0.03125f;  // 1/sqrt(1024)
    const int lane = threadIdx.x & 31, w = threadIdx.x >> 5;
    const int wm = (w & 1) * 64, wn = (w >> 1) * 32;
    const int gid = lane >> 2, tq = lane & 3;
    float* Pb = g_P + (size_t)b * SEQ * SEQ;

    #pragma unroll
    for (int mt = 0; mt < 4; ++mt)
        #pragma unroll
        for (int nt = 0; nt < 4; ++nt) {
            const int k = bk + wn + nt * 8 + tq * 2;
            #pragma unroll
            for (int half = 0; half < 2; ++half) {
                const int q = bq + wm + mt * 16 + gid + half * 8;
                const float v0 = acc[mt][nt][half * 2] * scale;
                const float v1 = acc[mt][nt][half * 2 + 1] * scale;
                float* prow = Pb + (size_t)q * SEQ;
                if (bk < bq) {
                    *(float2*)(prow + k) = make_float2(v0, v1);
                } else {
                    if (k     <= q) prow[k]     = v0;
                    if (k + 1 <= q) prow[k + 1] = v1;
                }
            }
        }
}

// ---------------------------------------------------------------------------
// Register softmax: one read, one fp16 hi/lo write, one exp per element.
// ---------------------------------------------------------------------------
__global__ __launch_bounds__(256) void k_softmax() {
    const int row = blockIdx.x;
    const int b = row >> 11, q = row & 2047;
    const size_t off = ((size_t)b * SEQ + q) * SEQ;
    const float* p = g_P + off;
    const int n = q + 1;

    const int tid = threadIdx.x, lane = tid & 31, wid = tid >> 5;
    __shared__ float red[8];

    float v[8];
    #pragma unroll
    for (int j = 0; j < 8; ++j) {
        const int k = j * 256 + tid;
        v[j] = (k < n) ? p[k] : -CUDART_INF_F;
    }

    float m = v[0];
    #pragma unroll
    for (int j = 1; j < 8; ++j) m = fmaxf(m, v[j]);
    #pragma unroll
    for (int o = 16; o > 0; o >>= 1) m = fmaxf(m, __shfl_xor_sync(0xffffffffu, m, o));
    if (lane == 0) red[wid] = m;
    __syncthreads();
    float rowmax = red[0];
    #pragma unroll
    for (int i = 1; i < 8; ++i) rowmax = fmaxf(rowmax, red[i]);
    __syncthreads();

    float s = 0.0f;
    #pragma unroll
    for (int j = 0; j < 8; ++j) {
        const float e = __expf(v[j] - rowmax);
        v[j] = e;
        s += e;
    }
    #pragma unroll
    for (int o = 16; o > 0; o >>= 1) s += __shfl_xor_sync(0xffffffffu, s, o);
    if (lane == 0) red[wid] = s;
    __syncthreads();
    float rowsum = 0.0f;
    #pragma unroll
    for (int i = 0; i < 8; ++i) rowsum += red[i];
    const float inv = 1.0f / rowsum;

    __half* ph = g_Phi + off;
    __half* pl = g_Plo + off;
    const int kend = (q & ~127) + 128;        // AV reads only up to here
    #pragma unroll
    for (int j = 0; j < 8; ++j) {
        const int k = j * 256 + tid;
        if (k < n) {
            const float wgt = v[j] * inv;
            const __half hi = __float2half_rn(wgt);
            ph[k] = hi;
            pl[k] = __float2half_rn(wgt - __half2float(hi));
        } else if (k < kend) {
            ph[k] = __float2half_rn(0.0f);
            pl[k] = __float2half_rn(0.0f);
        }
    }
}

// ---------------------------------------------------------------------------
// AV: out = P @ V (via V^T), K-loop clipped to q-tile end. Round 4 decimals.
// ---------------------------------------------------------------------------
__global__ __launch_bounds__(256, 1) void k_av(float* __restrict__ out) {
    const int bn = blockIdx.x * 128;
    const int bm = blockIdx.y * 128;
    const int b  = blockIdx.z;

    extern __shared__ char smem[];
    const uint32_t smem_u32 = smem_to_u32(smem);

    float acc[4][4][4] = {};
    const size_t po = ((size_t)b * SEQ + bm) * SEQ;
    const size_t vo = ((size_t)b << 21) + (size_t)bn * SEQ;
    mma_mainloop(smem_u32, g_Phi + po, g_Plo + po, SEQ,
                 g_Vt + vo, SEQ, bm + 128, acc);

    const int lane = threadIdx.x & 31, w = threadIdx.x >> 5;
    const int wm = (w & 1) * 64, wn = (w >> 1) * 32;
    const int gid = lane >> 2, tq = lane & 3;

    #pragma unroll
    for (int mt = 0; mt < 4; ++mt)
        #pragma unroll
        for (int nt = 0; nt < 4; ++nt) {
            const int c = bn + wn + nt * 8 + tq * 2;
            #pragma unroll
            for (int half = 0; half < 2; ++half) {
                const int q = bm + wm + mt * 16 + gid + half * 8;
                const float v0 = rintf(acc[mt][nt][half * 2]     * 1.0e4f) * 1.0e-4f;
                const float v1 = rintf(acc[mt][nt][half * 2 + 1] * 1.0e4f) * 1.0e-4f;
                *(float2*)(out + ((size_t)b * SEQ + q) * ADIM + c) = make_float2(v0, v1);
            }
        }
}

// ---------------------------------------------------------------------------
extern "C" void kernel_launch(void* const* d_in, const int* in_sizes, int n_in,
                              void* d_out, int out_size)
{
    const float* X  = (const float*)d_in[0];
    const float* Wk = (const float*)d_in[1];
    const float* Wq = (const float*)d_in[2];
    const float* Wv = (const float*)d_in[3];
    float* out = (float*)d_out;

    cudaFuncSetAttribute(k_qkv,    cudaFuncAttributeMaxDynamicSharedMemorySize, SMEM_BYTES);
    cudaFuncSetAttribute(k_scores, cudaFuncAttributeMaxDynamicSharedMemorySize, SMEM_BYTES);
    cudaFuncSetAttribute(k_av,     cudaFuncAttributeMaxDynamicSharedMemorySize, SMEM_BYTES);

    k_splitX<<<BSEQ * EMB / 1024, 256>>>(X);
    k_splitW<<<dim3(ADIM * EMB / 1024, 3), 256>>>(Wk, Wq, Wv);

    k_qkv<<<dim3(ADIM / 128, BSEQ / 128, 3), 256, SMEM_BYTES>>>();
    k_scores<<<dim3(SEQ / 128, SEQ / 128, BATCH), 256, SMEM_BYTES>>>();
    k_softmax<<<BSEQ, 256>>>();
    k_av<<<dim3(ADIM / 128, SEQ / 128, BATCH), 256, SMEM_BYTES>>>(out);
}